// round 4
// baseline (speedup 1.0000x reference)
#include <cuda_runtime.h>

typedef unsigned int u32;
typedef unsigned long long u64;

// ---- packed f32x2 helpers (Blackwell sm_103a) ------------------------------
__device__ __forceinline__ u64 pack2(float lo, float hi) {
    u64 r; asm("mov.b64 %0, {%1, %2};" : "=l"(r) : "f"(lo), "f"(hi)); return r;
}
__device__ __forceinline__ void unpack2(u64 v, float& lo, float& hi) {
    asm("mov.b64 {%0, %1}, %2;" : "=f"(lo), "=f"(hi) : "l"(v));
}
__device__ __forceinline__ void fma2(u64& d, u64 a, u64 b, u64 c) {
    asm("fma.rn.f32x2 %0, %1, %2, %3;" : "=l"(d) : "l"(a), "l"(b), "l"(c));
}

#define H2C 2654435761u
#define H3C 805459861u

// All weights in the constant bank (fastest per-kernel config, R2 evidence:
// warp-uniform LDC promotes to the uniform-const LDCU port, off L1tex).
// Filled by ONE pack-kernel + ONE memcpy node (5 memcpy nodes cost ~148us
// of graph replay; 1 costs ~30us).
#define OFF_S1 0
#define OFF_S2 2048
#define OFF_C1 3072
#define OFF_C2 5120
#define OFF_C3 9216
#define W_TOTAL 9408
__constant__ __align__(16) float CW[W_TOTAL];
__device__   __align__(16) float WPACK[W_TOTAL];

__global__ void pack_weights(const float* __restrict__ s1,
                             const float* __restrict__ s2,
                             const float* __restrict__ c1,
                             const float* __restrict__ c2,
                             const float* __restrict__ c3) {
    int t = blockIdx.x * 256 + threadIdx.x;
    if (t >= W_TOTAL) return;
    float v;
    if      (t < OFF_S2) v = s1[t - OFF_S1];
    else if (t < OFF_C1) v = s2[t - OFF_S2];
    else if (t < OFF_C2) v = c1[t - OFF_C1];
    else if (t < OFF_C3) v = c2[t - OFF_C2];
    else                 v = c3[t - OFF_C3];
    WPACK[t] = v;
}

__global__ void __launch_bounds__(128, 5) nerf_fused(
    const float* __restrict__ xin,     // (N,19)
    const float* __restrict__ grids,   // (16, 524288, 2)
    float* __restrict__ out,           // (N,4)
    int N)
{
    // xin staged through smem: coalesced loads, conflict-free LDS (19 ⊥ 32).
    __shared__ float sx[128 * 19];

    const int tid = threadIdx.x;
    {
        const int base = blockIdx.x * (128 * 19);
        const int lim  = N * 19;
        #pragma unroll
        for (int t = tid; t < 128 * 19; t += 128) {
            int g = base + t;
            sx[t] = (g < lim) ? xin[g] : 0.f;
        }
    }
    __syncthreads();

    const int i = blockIdx.x * 128 + tid;
    if (i >= N) return;

    const float px = sx[tid * 19 + 0];
    const float py = sx[tid * 19 + 1];
    const float pz = sx[tid * 19 + 2];

    // res = ceil(16 * s^l), s = float32(2^0.4) (rounded up) => 65/257/1025 at l=5/10/15.
    const int RES_[16]  = {16,22,28,37,49,65,85,112,148,195,257,338,446,589,777,1025};
    const u32 SZ_[16]   = {4096u,10648u,21952u,50656u,117656u,274632u,
                           524288u,524288u,524288u,524288u,524288u,
                           524288u,524288u,524288u,524288u,524288u};
    // MAX_DIRECT = 2

    // ---- phase A: hash-grid gather -> enc[32] (32 live regs, no fused acc) --
    float enc[32];
    #pragma unroll
    for (int l = 0; l < 16; l++) {
        const int R = RES_[l];
        const u32 S = SZ_[l];
        const float Rf = (float)R;
        float u = px * Rf, v = py * Rf, w = pz * Rf;
        float fu = floorf(u), fv = floorf(v), fw = floorf(w);
        float fx = u - fu, fy = v - fv, fz = w - fw;
        int ix = (int)fu, iy = (int)fv, iz = (int)fw;

        u32 idx[8];
        if (l <= 2) {
            #pragma unroll
            for (int j = 0; j < 8; j++) {
                int cx = ix + ((j >> 2) & 1);
                int cy = iy + ((j >> 1) & 1);
                int cz = iz + (j & 1);
                idx[j] = (u32)(cz * (R * R) + cy * R + cx) % S;
            }
        } else {
            u32 hx0 = (u32)ix;           u32 hx1 = hx0 + 1u;
            u32 hy0 = (u32)iy * H2C;     u32 hy1 = hy0 + H2C;
            u32 hz0 = (u32)iz * H3C;     u32 hz1 = hz0 + H3C;
            #pragma unroll
            for (int j = 0; j < 8; j++) {
                u32 h = ((j & 4) ? hx1 : hx0) ^ ((j & 2) ? hy1 : hy0) ^ ((j & 1) ? hz1 : hz0);
                idx[j] = (l >= 6) ? (h & 524287u) : (h % S);
            }
        }

        const float2* g = (const float2*)grids + (size_t)l * 524288u;
        float2 cc[8];
        #pragma unroll
        for (int j = 0; j < 8; j++) cc[j] = __ldg(g + idx[j]);

        const float gx = 1.f - fx, gy = 1.f - fy, gz = 1.f - fz;
        float c00x = cc[0].x*gx + cc[4].x*fx, c00y = cc[0].y*gx + cc[4].y*fx;
        float c01x = cc[1].x*gx + cc[5].x*fx, c01y = cc[1].y*gx + cc[5].y*fx;
        float c10x = cc[2].x*gx + cc[6].x*fx, c10y = cc[2].y*gx + cc[6].y*fx;
        float c11x = cc[3].x*gx + cc[7].x*fx, c11y = cc[3].y*gx + cc[7].y*fx;
        float c0x = c00x*gy + c10x*fy, c0y = c00y*gy + c10y*fy;
        float c1x = c01x*gy + c11x*fy, c1y = c01y*gy + c11y*fy;
        // NOTE: replicates reference bug: c0*(1-fz) + c1*fy   (fy, not fz!)
        enc[2*l]   = c0x*gz + c1x*fy;
        enc[2*l+1] = c0y*gz + c1y*fy;
    }

    // ---- phase B: gemm1 (32x64) + relu + gemm2 (64x16), half at a time -----
    // h1 is never fully materialized: each 32-wide half of h1 is folded into
    // the gemm2 accumulator immediately. Peak live: enc(32)+acc(32)+ov(16).
    u64 ovacc[8];
    #pragma unroll
    for (int j = 0; j < 8; j++) ovacc[j] = 0ull;

    const ulonglong2* W1 = (const ulonglong2*)(CW + OFF_S1);  // row k: 16 x u128
    const ulonglong2* W2 = (const ulonglong2*)(CW + OFF_S2);  // row m: 4  x u128

    #pragma unroll
    for (int half = 0; half < 2; half++) {
        u64 acc[16];
        #pragma unroll
        for (int j = 0; j < 16; j++) acc[j] = 0ull;
        #pragma unroll
        for (int k = 0; k < 32; k++) {
            u64 a = pack2(enc[k], enc[k]);
            #pragma unroll
            for (int j = 0; j < 8; j++) {
                ulonglong2 ww = W1[k*16 + half*8 + j];
                fma2(acc[2*j],   a, ww.x, acc[2*j]);
                fma2(acc[2*j+1], a, ww.y, acc[2*j+1]);
            }
        }
        #pragma unroll
        for (int q = 0; q < 16; q++) {
            float lo, hi; unpack2(acc[q], lo, hi);
            lo = fmaxf(lo, 0.f); hi = fmaxf(hi, 0.f);
            int m = half*32 + 2*q;
            u64 alo = pack2(lo, lo), ahi = pack2(hi, hi);
            #pragma unroll
            for (int j = 0; j < 4; j++) {
                ulonglong2 w0 = W2[m*4 + j];
                ulonglong2 w1 = W2[(m+1)*4 + j];
                fma2(ovacc[2*j],   alo, w0.x, ovacc[2*j]);
                fma2(ovacc[2*j+1], alo, w0.y, ovacc[2*j+1]);
                fma2(ovacc[2*j],   ahi, w1.x, ovacc[2*j]);
                fma2(ovacc[2*j+1], ahi, w1.y, ovacc[2*j+1]);
            }
        }
    }
    float ov[16];
    #pragma unroll
    for (int j = 0; j < 8; j++) unpack2(ovacc[j], ov[2*j], ov[2*j+1]);
    const float sigma = ov[0];

    // ---- phase C: gemm3 (32x64) + relu folded into gemm4 (64x64) -----------
    // ci = [direc(16) from smem, ov(16)]. hc halves folded straight into a4.
    u64 a4[32];
    #pragma unroll
    for (int j = 0; j < 32; j++) a4[j] = 0ull;

    const ulonglong2* Wc1 = (const ulonglong2*)(CW + OFF_C1);
    const ulonglong2* Wc2 = (const ulonglong2*)(CW + OFF_C2);

    #pragma unroll
    for (int half = 0; half < 2; half++) {
        u64 acc[16];
        #pragma unroll
        for (int j = 0; j < 16; j++) acc[j] = 0ull;
        #pragma unroll
        for (int k = 0; k < 32; k++) {
            float cik = (k < 16) ? sx[tid*19 + 3 + k] : ov[k - 16];
            u64 a = pack2(cik, cik);
            #pragma unroll
            for (int j = 0; j < 8; j++) {
                ulonglong2 ww = Wc1[k*16 + half*8 + j];
                fma2(acc[2*j],   a, ww.x, acc[2*j]);
                fma2(acc[2*j+1], a, ww.y, acc[2*j+1]);
            }
        }
        #pragma unroll
        for (int q = 0; q < 16; q++) {
            float lo, hi; unpack2(acc[q], lo, hi);
            lo = fmaxf(lo, 0.f); hi = fmaxf(hi, 0.f);
            int m = half*32 + 2*q;
            u64 alo = pack2(lo, lo), ahi = pack2(hi, hi);
            #pragma unroll
            for (int j = 0; j < 16; j++) {
                ulonglong2 w0 = Wc2[m*16 + j];
                ulonglong2 w1 = Wc2[(m+1)*16 + j];
                fma2(a4[2*j],   alo, w0.x, a4[2*j]);
                fma2(a4[2*j+1], alo, w0.y, a4[2*j+1]);
                fma2(a4[2*j],   ahi, w1.x, a4[2*j]);
                fma2(a4[2*j+1], ahi, w1.y, a4[2*j+1]);
            }
        }
    }

    // ---- phase D: relu + gemm5 (64x3) + sigmoid -----------------------------
    float col0 = 0.f, col1 = 0.f, col2 = 0.f;
    #pragma unroll
    for (int q = 0; q < 32; q++) {
        float lo, hi; unpack2(a4[q], lo, hi);
        lo = fmaxf(lo, 0.f); hi = fmaxf(hi, 0.f);
        int m = 2*q;
        col0 += lo * CW[OFF_C3 + m*3 + 0] + hi * CW[OFF_C3 + (m+1)*3 + 0];
        col1 += lo * CW[OFF_C3 + m*3 + 1] + hi * CW[OFF_C3 + (m+1)*3 + 1];
        col2 += lo * CW[OFF_C3 + m*3 + 2] + hi * CW[OFF_C3 + (m+1)*3 + 2];
    }

    col0 = 1.f / (1.f + expf(-col0));
    col1 = 1.f / (1.f + expf(-col1));
    col2 = 1.f / (1.f + expf(-col2));

    float4 r; r.x = col0; r.y = col1; r.z = col2; r.w = sigma;
    ((float4*)out)[i] = r;
}

extern "C" void kernel_launch(void* const* d_in, const int* in_sizes, int n_in,
                              void* d_out, int out_size) {
    const float* x     = (const float*)d_in[0];
    const float* grids = (const float*)d_in[1];
    const float* ws1   = (const float*)d_in[2];
    const float* ws2   = (const float*)d_in[3];
    const float* wc1   = (const float*)d_in[4];
    const float* wc2   = (const float*)d_in[5];
    const float* wc3   = (const float*)d_in[6];
    float* out = (float*)d_out;

    // 1) pack all weights into one contiguous device buffer (kernel node, cheap)
    pack_weights<<<(W_TOTAL + 255) / 256, 256>>>(ws1, ws2, wc1, wc2, wc3);

    // 2) ONE D2D memcpy node into the constant bank
    void* wpack_ptr = nullptr;
    cudaGetSymbolAddress(&wpack_ptr, WPACK);
    cudaMemcpyToSymbolAsync(CW, wpack_ptr, W_TOTAL * sizeof(float), 0,
                            cudaMemcpyDeviceToDevice, 0);

    // 3) main kernel
    const int N = in_sizes[0] / 19;
    const int blocks = (N + 127) / 128;
    nerf_fused<<<blocks, 128>>>(x, grids, out, N);
}

// round 5
// speedup vs baseline: 1.3403x; 1.3403x over previous
#include <cuda_runtime.h>

typedef unsigned int u32;
typedef unsigned long long u64;

// ---- packed f32x2 helpers (Blackwell sm_103a) ------------------------------
__device__ __forceinline__ u64 pack2(float lo, float hi) {
    u64 r; asm("mov.b64 %0, {%1, %2};" : "=l"(r) : "f"(lo), "f"(hi)); return r;
}
__device__ __forceinline__ void unpack2(u64 v, float& lo, float& hi) {
    asm("mov.b64 {%0, %1}, %2;" : "=f"(lo), "=f"(hi) : "l"(v));
}
__device__ __forceinline__ void fma2(u64& d, u64 a, u64 b, u64 c) {
    asm("fma.rn.f32x2 %0, %1, %2, %3;" : "=l"(d) : "l"(a), "l"(b), "l"(c));
}

#define H2C 2654435761u
#define H3C 805459861u

// Weight traffic is split ~50/50 between the constant port (LDC, kappa~13.4
// cyc/LDC.128/SMSP measured R2) and the L1tex port (LDS broadcast, ~2.1 cyc,
// measured R1/R3). Split is per-j-loop (output halves) so EVERY warp drives
// both ports concurrently. Const bank holds the full pack (one pack kernel +
// one memcpy node ~ +35us wall); smem holds the upper output-halves.
#define OFF_S1 0
#define OFF_S2 2048
#define OFF_C1 3072
#define OFF_C2 5120
#define OFF_C3 9216
#define W_TOTAL 9408
__constant__ __align__(16) float CW[W_TOTAL];
__device__   __align__(16) float WPACK[W_TOTAL];

__global__ void pack_weights(const float* __restrict__ s1,
                             const float* __restrict__ s2,
                             const float* __restrict__ c1,
                             const float* __restrict__ c2,
                             const float* __restrict__ c3) {
    int t = blockIdx.x * 256 + threadIdx.x;
    if (t >= W_TOTAL) return;
    float v;
    if      (t < OFF_S2) v = s1[t - OFF_S1];
    else if (t < OFF_C1) v = s2[t - OFF_S2];
    else if (t < OFF_C2) v = c1[t - OFF_C1];
    else if (t < OFF_C3) v = c2[t - OFF_C2];
    else                 v = c3[t - OFF_C3];
    WPACK[t] = v;
}

__global__ void __launch_bounds__(128, 4) nerf_fused(
    const float* __restrict__ xin,     // (N,19)
    const float* __restrict__ grids,   // (16, 524288, 2)
    const float* __restrict__ gw_s1,   // (32,64)
    const float* __restrict__ gw_s2,   // (64,16)
    const float* __restrict__ gw_c1,   // (32,64)
    const float* __restrict__ gw_c2,   // (64,64)
    float* __restrict__ out,           // (N,4)
    int N)
{
    // smem weight halves: upper output columns of each matrix.
    __shared__ __align__(16) ulonglong2 W1s[32 * 8];  // s1 cols 32..63
    __shared__ __align__(16) ulonglong2 W2s[64 * 2];  // s2 cols  8..15
    __shared__ __align__(16) ulonglong2 W3s[32 * 8];  // c1 cols 32..63
    __shared__ __align__(16) ulonglong2 W4s[64 * 8];  // c2 cols 32..63
    // xin staged: coalesced loads, conflict-free LDS (19 coprime 32).
    __shared__ float sx[128 * 19];

    const int tid = threadIdx.x;
    {
        float* w1f = (float*)W1s;
        float* w2f = (float*)W2s;
        float* w3f = (float*)W3s;
        float* w4f = (float*)W4s;
        for (int t = tid; t < 1024; t += 128) {          // 32 rows x 32 cols
            int r = t >> 5, c = t & 31;
            w1f[t] = gw_s1[r * 64 + 32 + c];
            w3f[t] = gw_c1[r * 64 + 32 + c];
        }
        for (int t = tid; t < 512; t += 128) {           // 64 rows x 8 cols
            int r = t >> 3, c = t & 7;
            w2f[t] = gw_s2[r * 16 + 8 + c];
        }
        for (int t = tid; t < 2048; t += 128) {          // 64 rows x 32 cols
            int r = t >> 5, c = t & 31;
            w4f[t] = gw_c2[r * 64 + 32 + c];
        }
        const int base = blockIdx.x * (128 * 19);
        const int lim  = N * 19;
        #pragma unroll
        for (int t = tid; t < 128 * 19; t += 128) {
            int g = base + t;
            sx[t] = (g < lim) ? xin[g] : 0.f;
        }
    }
    __syncthreads();

    const int i = blockIdx.x * 128 + tid;
    if (i >= N) return;

    const float px = sx[tid * 19 + 0];
    const float py = sx[tid * 19 + 1];
    const float pz = sx[tid * 19 + 2];

    // res = ceil(16 * s^l), s = float32(2^0.4) (rounded up) => 65/257/1025 at l=5/10/15.
    const int RES_[16]  = {16,22,28,37,49,65,85,112,148,195,257,338,446,589,777,1025};
    const u32 SZ_[16]   = {4096u,10648u,21952u,50656u,117656u,274632u,
                           524288u,524288u,524288u,524288u,524288u,
                           524288u,524288u,524288u,524288u,524288u};
    // MAX_DIRECT = 2

    // ---- phase A: gather fused with gemm1 (32x64) ---------------------------
    // acc[q] holds h1 columns (2q, 2q+1). Columns 0..31 fed from const,
    // columns 32..63 fed from smem (dual-port every level).
    u64 acc[32];
    #pragma unroll
    for (int j = 0; j < 32; j++) acc[j] = 0ull;

    const ulonglong2* W1c = (const ulonglong2*)(CW + OFF_S1);  // row k: 16 x u128

    #pragma unroll
    for (int l = 0; l < 16; l++) {
        const int R = RES_[l];
        const u32 S = SZ_[l];
        const float Rf = (float)R;
        float u = px * Rf, v = py * Rf, w = pz * Rf;
        float fu = floorf(u), fv = floorf(v), fw = floorf(w);
        float fx = u - fu, fy = v - fv, fz = w - fw;
        int ix = (int)fu, iy = (int)fv, iz = (int)fw;

        u32 idx[8];
        if (l <= 2) {
            #pragma unroll
            for (int j = 0; j < 8; j++) {
                int cx = ix + ((j >> 2) & 1);
                int cy = iy + ((j >> 1) & 1);
                int cz = iz + (j & 1);
                idx[j] = (u32)(cz * (R * R) + cy * R + cx) % S;
            }
        } else {
            u32 hx0 = (u32)ix;           u32 hx1 = hx0 + 1u;
            u32 hy0 = (u32)iy * H2C;     u32 hy1 = hy0 + H2C;
            u32 hz0 = (u32)iz * H3C;     u32 hz1 = hz0 + H3C;
            #pragma unroll
            for (int j = 0; j < 8; j++) {
                u32 h = ((j & 4) ? hx1 : hx0) ^ ((j & 2) ? hy1 : hy0) ^ ((j & 1) ? hz1 : hz0);
                idx[j] = (l >= 6) ? (h & 524287u) : (h % S);
            }
        }

        const float2* g = (const float2*)grids + (size_t)l * 524288u;
        float2 cc[8];
        #pragma unroll
        for (int j = 0; j < 8; j++) cc[j] = __ldg(g + idx[j]);

        const float gx = 1.f - fx, gy = 1.f - fy, gz = 1.f - fz;
        float c00x = cc[0].x*gx + cc[4].x*fx, c00y = cc[0].y*gx + cc[4].y*fx;
        float c01x = cc[1].x*gx + cc[5].x*fx, c01y = cc[1].y*gx + cc[5].y*fx;
        float c10x = cc[2].x*gx + cc[6].x*fx, c10y = cc[2].y*gx + cc[6].y*fx;
        float c11x = cc[3].x*gx + cc[7].x*fx, c11y = cc[3].y*gx + cc[7].y*fx;
        float c0x = c00x*gy + c10x*fy, c0y = c00y*gy + c10y*fy;
        float c1x = c01x*gy + c11x*fy, c1y = c01y*gy + c11y*fy;
        // NOTE: replicates reference bug: c0*(1-fz) + c1*fy   (fy, not fz!)
        float fex = c0x*gz + c1x*fy;
        float fey = c0y*gz + c1y*fy;

        u64 a0 = pack2(fex, fex);
        u64 a1 = pack2(fey, fey);
        #pragma unroll
        for (int j = 0; j < 8; j++) {
            // const half: columns 4j..4j+3  -> acc[2j], acc[2j+1]
            ulonglong2 w0 = W1c[(2*l)   * 16 + j];
            ulonglong2 w1 = W1c[(2*l+1) * 16 + j];
            fma2(acc[2*j],   a0, w0.x, acc[2*j]);
            fma2(acc[2*j+1], a0, w0.y, acc[2*j+1]);
            fma2(acc[2*j],   a1, w1.x, acc[2*j]);
            fma2(acc[2*j+1], a1, w1.y, acc[2*j+1]);
            // smem half: columns 32+4j..35+4j -> acc[16+2j], acc[16+2j+1]
            ulonglong2 s0 = W1s[(2*l)   * 8 + j];
            ulonglong2 s1v = W1s[(2*l+1) * 8 + j];
            fma2(acc[16+2*j],   a0, s0.x,  acc[16+2*j]);
            fma2(acc[16+2*j+1], a0, s0.y,  acc[16+2*j+1]);
            fma2(acc[16+2*j],   a1, s1v.x, acc[16+2*j]);
            fma2(acc[16+2*j+1], a1, s1v.y, acc[16+2*j+1]);
        }
    }

    // ---- phase B: relu(h1) folded into gemm2 (64x16), dual-port -------------
    u64 ovacc[8];
    #pragma unroll
    for (int j = 0; j < 8; j++) ovacc[j] = 0ull;
    const ulonglong2* W2c = (const ulonglong2*)(CW + OFF_S2);  // row m: 4 x u128

    #pragma unroll
    for (int q = 0; q < 32; q++) {
        float lo, hi; unpack2(acc[q], lo, hi);
        lo = fmaxf(lo, 0.f); hi = fmaxf(hi, 0.f);
        int m = 2*q;
        u64 alo = pack2(lo, lo), ahi = pack2(hi, hi);
        #pragma unroll
        for (int j = 0; j < 2; j++) {
            // const: out cols 4j..4j+3 -> ovacc[2j], ovacc[2j+1]
            ulonglong2 w0 = W2c[m*4 + j];
            ulonglong2 w1 = W2c[(m+1)*4 + j];
            fma2(ovacc[2*j],   alo, w0.x, ovacc[2*j]);
            fma2(ovacc[2*j+1], alo, w0.y, ovacc[2*j+1]);
            fma2(ovacc[2*j],   ahi, w1.x, ovacc[2*j]);
            fma2(ovacc[2*j+1], ahi, w1.y, ovacc[2*j+1]);
            // smem: out cols 8+4j..11+4j -> ovacc[4+2j], ovacc[4+2j+1]
            ulonglong2 s0 = W2s[m*2 + j];
            ulonglong2 s1v = W2s[(m+1)*2 + j];
            fma2(ovacc[4+2*j],   alo, s0.x,  ovacc[4+2*j]);
            fma2(ovacc[4+2*j+1], alo, s0.y,  ovacc[4+2*j+1]);
            fma2(ovacc[4+2*j],   ahi, s1v.x, ovacc[4+2*j]);
            fma2(ovacc[4+2*j+1], ahi, s1v.y, ovacc[4+2*j+1]);
        }
    }
    float ov[16];
    #pragma unroll
    for (int j = 0; j < 8; j++) unpack2(ovacc[j], ov[2*j], ov[2*j+1]);
    const float sigma = ov[0];

    // ---- phase C: gemm3 (32x64) streamed into gemm4 (64x64), dual-port ------
    u64 a4[32];
    #pragma unroll
    for (int j = 0; j < 32; j++) a4[j] = 0ull;
    const ulonglong2* W3c = (const ulonglong2*)(CW + OFF_C1);
    const ulonglong2* W4c = (const ulonglong2*)(CW + OFF_C2);

    u64 acc3[32];
    #pragma unroll
    for (int j = 0; j < 32; j++) acc3[j] = 0ull;
    #pragma unroll
    for (int k = 0; k < 32; k++) {
        float cik = (k < 16) ? sx[tid*19 + 3 + k] : ov[k - 16];
        u64 a = pack2(cik, cik);
        #pragma unroll
        for (int j = 0; j < 8; j++) {
            ulonglong2 w0 = W3c[k*16 + j];       // cols 4j..4j+3
            fma2(acc3[2*j],   a, w0.x, acc3[2*j]);
            fma2(acc3[2*j+1], a, w0.y, acc3[2*j+1]);
            ulonglong2 s0 = W3s[k*8 + j];        // cols 32+4j..
            fma2(acc3[16+2*j],   a, s0.x, acc3[16+2*j]);
            fma2(acc3[16+2*j+1], a, s0.y, acc3[16+2*j+1]);
        }
    }
    // relu(hc) streamed into gemm4: hc row m = 2q, 2q+1
    #pragma unroll
    for (int q = 0; q < 32; q++) {
        float lo, hi; unpack2(acc3[q], lo, hi);
        lo = fmaxf(lo, 0.f); hi = fmaxf(hi, 0.f);
        int m = 2*q;
        u64 alo = pack2(lo, lo), ahi = pack2(hi, hi);
        #pragma unroll
        for (int j = 0; j < 8; j++) {
            ulonglong2 w0 = W4c[m*16 + j];
            ulonglong2 w1 = W4c[(m+1)*16 + j];
            fma2(a4[2*j],   alo, w0.x, a4[2*j]);
            fma2(a4[2*j+1], alo, w0.y, a4[2*j+1]);
            fma2(a4[2*j],   ahi, w1.x, a4[2*j]);
            fma2(a4[2*j+1], ahi, w1.y, a4[2*j+1]);
            ulonglong2 s0 = W4s[m*8 + j];
            ulonglong2 s1v = W4s[(m+1)*8 + j];
            fma2(a4[16+2*j],   alo, s0.x,  a4[16+2*j]);
            fma2(a4[16+2*j+1], alo, s0.y,  a4[16+2*j+1]);
            fma2(a4[16+2*j],   ahi, s1v.x, a4[16+2*j]);
            fma2(a4[16+2*j+1], ahi, s1v.y, a4[16+2*j+1]);
        }
    }

    // ---- phase D: relu + gemm5 (64x3, const) + sigmoid ----------------------
    float col0 = 0.f, col1 = 0.f, col2 = 0.f;
    #pragma unroll
    for (int q = 0; q < 32; q++) {
        float lo, hi; unpack2(a4[q], lo, hi);
        lo = fmaxf(lo, 0.f); hi = fmaxf(hi, 0.f);
        int m = 2*q;
        col0 += lo * CW[OFF_C3 + m*3 + 0] + hi * CW[OFF_C3 + (m+1)*3 + 0];
        col1 += lo * CW[OFF_C3 + m*3 + 1] + hi * CW[OFF_C3 + (m+1)*3 + 1];
        col2 += lo * CW[OFF_C3 + m*3 + 2] + hi * CW[OFF_C3 + (m+1)*3 + 2];
    }

    col0 = 1.f / (1.f + expf(-col0));
    col1 = 1.f / (1.f + expf(-col1));
    col2 = 1.f / (1.f + expf(-col2));

    float4 r; r.x = col0; r.y = col1; r.z = col2; r.w = sigma;
    ((float4*)out)[i] = r;
}

extern "C" void kernel_launch(void* const* d_in, const int* in_sizes, int n_in,
                              void* d_out, int out_size) {
    const float* x     = (const float*)d_in[0];
    const float* grids = (const float*)d_in[1];
    const float* ws1   = (const float*)d_in[2];
    const float* ws2   = (const float*)d_in[3];
    const float* wc1   = (const float*)d_in[4];
    const float* wc2   = (const float*)d_in[5];
    const float* wc3   = (const float*)d_in[6];
    float* out = (float*)d_out;

    // pack all weights into one device buffer, then ONE memcpy node to const.
    pack_weights<<<(W_TOTAL + 255) / 256, 256>>>(ws1, ws2, wc1, wc2, wc3);
    void* wpack_ptr = nullptr;
    cudaGetSymbolAddress(&wpack_ptr, WPACK);
    cudaMemcpyToSymbolAsync(CW, wpack_ptr, W_TOTAL * sizeof(float), 0,
                            cudaMemcpyDeviceToDevice, 0);

    const int N = in_sizes[0] / 19;
    const int blocks = (N + 127) / 128;
    nerf_fused<<<blocks, 128>>>(x, grids, ws1, ws2, wc1, wc2, out, N);
}